// round 12
// baseline (speedup 1.0000x reference)
#include <cuda_runtime.h>
#include <cuda_bf16.h>

// ROI pooling (crop + 7x7 bilinear resize), NHWC.
// img:  (1, 128, 128, 1024) fp32
// rois: (1, 1000, 4) int32  -> {x, y, w, h}
// out:  (1, 1000, 7, 7, 1024) fp32
//
// Single-wavefront loads: each thread handles 4 scalar floats at channel
// c + {0,128,256,384}; warp lanes are consecutive 4B -> every LDG.32/STG.32
// is exactly one 128B L1 wavefront (1.0 cyc cross-LDG service instead of
// 2.07 cyc/wf within-LDG replays of LDG.128).
// 128-thread CTAs, grid (7000,2); precomputed per-px offsets/weights in regs;
// depth-1 load lookahead.

#define H_IMG 128
#define W_IMG 128
#define C_IMG 1024
#define POOL 7
#define NUM_ROIS 1000

__global__ __launch_bounds__(128, 8)
void roi_pool_kernel(const float* __restrict__ img,
                     const int*   __restrict__ rois,
                     float*       __restrict__ out)
{
    const int b  = blockIdx.x;            // 0 .. 6999
    const int py = b % POOL;
    const int r  = b / POOL;
    // Base float channel for this thread: tid + 512*half; chunks at +0/128/256/384.
    const int c  = threadIdx.x + (blockIdx.y << 9);

    const int4 roi = __ldg(((const int4*)rois) + r);
    const int rx = roi.x, ry = roi.y, rw = roi.z, rh = roi.w;

    // y axis (uniform across CTA)
    const float hf = (float)rh;
    float fy = (py + 0.5f) * (hf * (1.0f / POOL)) - 0.5f;
    fy = fminf(fmaxf(fy, 0.0f), fmaxf(hf - 1.0f, 0.0f));
    int   iy0 = (int)floorf(fy);
    const float wy  = fy - (float)iy0;
    const float wy1 = 1.0f - wy;
    int   iy1 = min(iy0 + 1, rh - 1);
    iy0 += ry;  iy1 += ry;

    const float* __restrict__ row0 = img + ((size_t)iy0 * W_IMG) * C_IMG + c;
    const float* __restrict__ row1 = img + ((size_t)iy1 * W_IMG) * C_IMG + c;

    // x axis scalars (uniform)
    const float wf  = (float)rw;
    const float sfx = wf * (1.0f / POOL);
    const float xcl = fmaxf(wf - 1.0f, 0.0f);

    // Precompute per-px column offsets (float units) and 4 bilinear weights.
    int   o0[POOL], o1[POOL];
    float w00[POOL], w01[POOL], w10[POOL], w11[POOL];
    #pragma unroll
    for (int px = 0; px < POOL; ++px) {
        float fx = (px + 0.5f) * sfx - 0.5f;
        fx = fminf(fmaxf(fx, 0.0f), xcl);
        int   ix0 = (int)floorf(fx);
        const float wx  = fx - (float)ix0;
        const float wx1 = 1.0f - wx;
        int   ix1 = min(ix0 + 1, rw - 1);
        o0[px] = (rx + ix0) * C_IMG;
        o1[px] = (rx + ix1) * C_IMG;
        w00[px] = wx1 * wy1;
        w01[px] = wx  * wy1;
        w10[px] = wx1 * wy;
        w11[px] = wx  * wy;
    }

    float* __restrict__ optr =
        out + ((size_t)(r * POOL + py) * POOL) * C_IMG + c;

    // Pipelined px loop, depth 1. All loads/stores are single-wavefront LDG.32/
    // STG.32 with immediate chunk offsets (+0/+128/+256/+384 floats).
    float v00[4], v01[4], v10[4], v11[4];
    #pragma unroll
    for (int k = 0; k < 4; ++k) {
        v00[k] = __ldg(row0 + o0[0] + k * 128);
        v01[k] = __ldg(row0 + o1[0] + k * 128);
        v10[k] = __ldg(row1 + o0[0] + k * 128);
        v11[k] = __ldg(row1 + o1[0] + k * 128);
    }

    #pragma unroll
    for (int px = 0; px < POOL; ++px) {
        float n00[4], n01[4], n10[4], n11[4];
        if (px + 1 < POOL) {
            const int p0 = o0[px + 1], p1 = o1[px + 1];
            #pragma unroll
            for (int k = 0; k < 4; ++k) {
                n00[k] = __ldg(row0 + p0 + k * 128);
                n01[k] = __ldg(row0 + p1 + k * 128);
                n10[k] = __ldg(row1 + p0 + k * 128);
                n11[k] = __ldg(row1 + p1 + k * 128);
            }
        }

        const float a = w00[px], bb = w01[px];
        const float cc = w10[px], d = w11[px];
        float* op = optr + (size_t)px * C_IMG;
        #pragma unroll
        for (int k = 0; k < 4; ++k) {
            const float o =
                v00[k] * a + v01[k] * bb + v10[k] * cc + v11[k] * d;
            __stcs(op + k * 128, o);
        }

        #pragma unroll
        for (int k = 0; k < 4; ++k) {
            v00[k] = n00[k]; v01[k] = n01[k];
            v10[k] = n10[k]; v11[k] = n11[k];
        }
    }
}

extern "C" void kernel_launch(void* const* d_in, const int* in_sizes, int n_in,
                              void* d_out, int out_size)
{
    const float* img  = (const float*)d_in[0];
    const int*   rois = (const int*)d_in[1];
    float*       out  = (float*)d_out;

    dim3 grid(NUM_ROIS * POOL, 2);
    dim3 block(128);
    roi_pool_kernel<<<grid, block>>>(img, rois, out);
}

// round 13
// speedup vs baseline: 1.0946x; 1.0946x over previous
#include <cuda_runtime.h>
#include <cuda_bf16.h>
#include <cstdint>

// ROI pooling (crop + 7x7 bilinear resize), NHWC.
// img:  (1, 128, 128, 1024) fp32
// rois: (1, 1000, 4) int32  -> {x, y, w, h}
// out:  (1, 1000, 7, 7, 1024) fp32
//
// One CTA per (roi, py); 256 threads x float4 covers C=1024.
// Compute into a 28KB smem row buffer (STS -> smem crossbar, off the L1tex
// global queue), then ONE cp.async.bulk smem->gmem store of the whole row
// via the TMA engine. Read path unchanged from the champion (precomputed
// reg-resident offsets/weights, depth-1 LDG.128 lookahead).

#define H_IMG 128
#define W_IMG 128
#define C_IMG 1024
#define POOL 7
#define NUM_ROIS 1000
#define CPP (C_IMG / 4)          // float4s per pixel = 256
#define ROW_BYTES (POOL * C_IMG * 4)   // 28672

__global__ __launch_bounds__(256, 4)
void roi_pool_kernel(const float* __restrict__ img,
                     const int*   __restrict__ rois,
                     float*       __restrict__ out)
{
    __shared__ alignas(128) float4 sbuf[POOL * CPP];   // 28 KB

    const int b  = blockIdx.x;            // 0 .. 6999
    const int py = b % POOL;
    const int r  = b / POOL;
    const int c4 = threadIdx.x;           // float4 channel index, 0..255

    const int4 roi = __ldg(((const int4*)rois) + r);
    const int rx = roi.x, ry = roi.y, rw = roi.z, rh = roi.w;

    // y axis (uniform across CTA)
    const float hf = (float)rh;
    float fy = (py + 0.5f) * (hf * (1.0f / POOL)) - 0.5f;
    fy = fminf(fmaxf(fy, 0.0f), fmaxf(hf - 1.0f, 0.0f));
    int   iy0 = (int)floorf(fy);
    const float wy  = fy - (float)iy0;
    const float wy1 = 1.0f - wy;
    int   iy1 = min(iy0 + 1, rh - 1);
    iy0 += ry;  iy1 += ry;

    const float4* __restrict__ row0 =
        (const float4*)(img + ((size_t)iy0 * W_IMG) * C_IMG) + c4;
    const float4* __restrict__ row1 =
        (const float4*)(img + ((size_t)iy1 * W_IMG) * C_IMG) + c4;

    // x axis scalars (uniform)
    const float wf  = (float)rw;
    const float sfx = wf * (1.0f / POOL);
    const float xcl = fmaxf(wf - 1.0f, 0.0f);

    // Precompute per-px column offsets and the 4 bilinear weights (all uniform).
    int   o0[POOL], o1[POOL];
    float w00[POOL], w01[POOL], w10[POOL], w11[POOL];
    #pragma unroll
    for (int px = 0; px < POOL; ++px) {
        float fx = (px + 0.5f) * sfx - 0.5f;
        fx = fminf(fmaxf(fx, 0.0f), xcl);
        int   ix0 = (int)floorf(fx);
        const float wx  = fx - (float)ix0;
        const float wx1 = 1.0f - wx;
        int   ix1 = min(ix0 + 1, rw - 1);
        o0[px] = (rx + ix0) * CPP;
        o1[px] = (rx + ix1) * CPP;
        w00[px] = wx1 * wy1;
        w01[px] = wx  * wy1;
        w10[px] = wx1 * wy;
        w11[px] = wx  * wy;
    }

    // Software-pipelined px loop: loads for px+1 issue before math of px.
    float4 v00 = __ldg(row0 + o0[0]);
    float4 v01 = __ldg(row0 + o1[0]);
    float4 v10 = __ldg(row1 + o0[0]);
    float4 v11 = __ldg(row1 + o1[0]);

    #pragma unroll
    for (int px = 0; px < POOL; ++px) {
        float4 n00, n01, n10, n11;
        if (px + 1 < POOL) {
            const int p0 = o0[px + 1], p1 = o1[px + 1];
            n00 = __ldg(row0 + p0);
            n01 = __ldg(row0 + p1);
            n10 = __ldg(row1 + p0);
            n11 = __ldg(row1 + p1);
        }

        const float a = w00[px], bb = w01[px];
        const float c = w10[px], d  = w11[px];
        float4 o;
        o.x = v00.x * a + v01.x * bb + v10.x * c + v11.x * d;
        o.y = v00.y * a + v01.y * bb + v10.y * c + v11.y * d;
        o.z = v00.z * a + v01.z * bb + v10.z * c + v11.z * d;
        o.w = v00.w * a + v01.w * bb + v10.w * c + v11.w * d;

        sbuf[px * CPP + c4] = o;           // STS.128, conflict-free

        v00 = n00; v01 = n01; v10 = n10; v11 = n11;
    }

    __syncthreads();

    // One bulk smem->gmem store of the whole 28KB row via the TMA engine.
    if (threadIdx.x == 0) {
        // Make the generic-proxy smem writes visible to the async proxy.
        asm volatile("fence.proxy.async.shared::cta;" ::: "memory");

        uint32_t s_addr;
        asm("{ .reg .u64 t; cvta.to.shared.u64 t, %1; cvt.u32.u64 %0, t; }"
            : "=r"(s_addr) : "l"(sbuf));
        float* gptr = out + (size_t)(r * POOL + py) * POOL * C_IMG;

        asm volatile(
            "cp.async.bulk.global.shared::cta.bulk_group [%0], [%1], %2;"
            :: "l"(gptr), "r"(s_addr), "n"(ROW_BYTES) : "memory");
        asm volatile("cp.async.bulk.commit_group;" ::: "memory");
        asm volatile("cp.async.bulk.wait_group 0;" ::: "memory");
    }
}

extern "C" void kernel_launch(void* const* d_in, const int* in_sizes, int n_in,
                              void* d_out, int out_size)
{
    const float* img  = (const float*)d_in[0];
    const int*   rois = (const int*)d_in[1];
    float*       out  = (float*)d_out;

    dim3 grid(NUM_ROIS * POOL);
    dim3 block(256);
    roi_pool_kernel<<<grid, block>>>(img, rois, out);
}

// round 14
// speedup vs baseline: 1.2306x; 1.1243x over previous
#include <cuda_runtime.h>
#include <cuda_bf16.h>

// ROI pooling (crop + 7x7 bilinear resize), NHWC.
// img:  (1, 128, 128, 1024) fp32
// rois: (1, 1000, 4) int32  -> {x, y, w, h}
// out:  (1, 1000, 7, 7, 1024) fp32
//
// Champion per-warp structure (precomputed per-px offsets + 4 weights,
// depth-1 LDG.128 lookahead, __stcs) at the finest useful CTA granularity:
// 64-thread CTAs, grid (7000,4); blockIdx.y picks the channel quarter.
// 16 CTAs/SM x 2 warps -> maximally desynchronized load bursts.

#define H_IMG 128
#define W_IMG 128
#define C_IMG 1024
#define POOL 7
#define NUM_ROIS 1000
#define CPP (C_IMG / 4)   // float4s per pixel = 256

__global__ __launch_bounds__(64, 16)
void roi_pool_kernel(const float* __restrict__ img,
                     const int*   __restrict__ rois,
                     float*       __restrict__ out)
{
    const int b  = blockIdx.x;            // 0 .. 6999
    const int py = b % POOL;
    const int r  = b / POOL;
    const int c4 = threadIdx.x + (blockIdx.y << 6);   // 0..255 float4 channel

    const int4 roi = __ldg(((const int4*)rois) + r);
    const int rx = roi.x, ry = roi.y, rw = roi.z, rh = roi.w;

    // y axis (uniform across CTA)
    const float hf = (float)rh;
    float fy = (py + 0.5f) * (hf * (1.0f / POOL)) - 0.5f;
    fy = fminf(fmaxf(fy, 0.0f), fmaxf(hf - 1.0f, 0.0f));
    int   iy0 = (int)floorf(fy);
    const float wy  = fy - (float)iy0;
    const float wy1 = 1.0f - wy;
    int   iy1 = min(iy0 + 1, rh - 1);
    iy0 += ry;  iy1 += ry;

    const float4* __restrict__ row0 =
        (const float4*)(img + ((size_t)iy0 * W_IMG) * C_IMG) + c4;
    const float4* __restrict__ row1 =
        (const float4*)(img + ((size_t)iy1 * W_IMG) * C_IMG) + c4;

    // x axis scalars (uniform)
    const float wf  = (float)rw;
    const float sfx = wf * (1.0f / POOL);
    const float xcl = fmaxf(wf - 1.0f, 0.0f);

    // Precompute per-px column offsets and the 4 bilinear weights (all uniform).
    int   o0[POOL], o1[POOL];
    float w00[POOL], w01[POOL], w10[POOL], w11[POOL];
    #pragma unroll
    for (int px = 0; px < POOL; ++px) {
        float fx = (px + 0.5f) * sfx - 0.5f;
        fx = fminf(fmaxf(fx, 0.0f), xcl);
        int   ix0 = (int)floorf(fx);
        const float wx  = fx - (float)ix0;
        const float wx1 = 1.0f - wx;
        int   ix1 = min(ix0 + 1, rw - 1);
        o0[px] = (rx + ix0) * CPP;
        o1[px] = (rx + ix1) * CPP;
        w00[px] = wx1 * wy1;
        w01[px] = wx  * wy1;
        w10[px] = wx1 * wy;
        w11[px] = wx  * wy;
    }

    float4* __restrict__ optr =
        (float4*)out + ((size_t)(r * POOL + py) * POOL) * CPP + c4;

    // Software-pipelined px loop: loads for px+1 issue before math of px.
    float4 v00 = __ldg(row0 + o0[0]);
    float4 v01 = __ldg(row0 + o1[0]);
    float4 v10 = __ldg(row1 + o0[0]);
    float4 v11 = __ldg(row1 + o1[0]);

    #pragma unroll
    for (int px = 0; px < POOL; ++px) {
        float4 n00, n01, n10, n11;
        if (px + 1 < POOL) {
            const int p0 = o0[px + 1], p1 = o1[px + 1];
            n00 = __ldg(row0 + p0);
            n01 = __ldg(row0 + p1);
            n10 = __ldg(row1 + p0);
            n11 = __ldg(row1 + p1);
        }

        const float a = w00[px], bb = w01[px];
        const float c = w10[px], d  = w11[px];
        float4 o;
        o.x = v00.x * a + v01.x * bb + v10.x * c + v11.x * d;
        o.y = v00.y * a + v01.y * bb + v10.y * c + v11.y * d;
        o.z = v00.z * a + v01.z * bb + v10.z * c + v11.z * d;
        o.w = v00.w * a + v01.w * bb + v10.w * c + v11.w * d;

        __stcs(optr + (size_t)px * CPP, o);

        v00 = n00; v01 = n01; v10 = n10; v11 = n11;
    }
}

extern "C" void kernel_launch(void* const* d_in, const int* in_sizes, int n_in,
                              void* d_out, int out_size)
{
    const float* img  = (const float*)d_in[0];
    const int*   rois = (const int*)d_in[1];
    float*       out  = (float*)d_out;

    dim3 grid(NUM_ROIS * POOL, 4);
    dim3 block(64);
    roi_pool_kernel<<<grid, block>>>(img, rois, out);
}